// round 9
// baseline (speedup 1.0000x reference)
#include <cuda_runtime.h>
#include <cuda_bf16.h>
#include <cstdint>
#include <math.h>

// Problem constants
#define B_ 4
#define T_ 2048
#define C_ 1024
#define H_ 16
#define D_ 64
#define M_ (B_ * T_)          // 8192 rows
#define QKV_N (3 * C_)        // 3072

// Scratch (tf32 bit patterns in f32 containers, except final output)
__device__ float g_qkv[(size_t)M_ * QKV_N];
__device__ float g_ctx[(size_t)M_ * C_];
__device__ float g_xc[(size_t)M_ * C_];
__device__ float g_w1[(size_t)QKV_N * C_];
__device__ float g_w2[(size_t)C_ * C_];

// ===========================================================================
// helpers
// ===========================================================================
__device__ __forceinline__ uint32_t smem_u32(const void* p) {
    uint32_t a;
    asm("{ .reg .u64 t; cvta.to.shared.u64 t, %1; cvt.u32.u64 %0, t; }"
        : "=r"(a) : "l"(p));
    return a;
}

__device__ __forceinline__ void cp16(uint32_t dst, const void* src) {
    asm volatile("cp.async.cg.shared.global [%0], [%1], 16;"
        :: "r"(dst), "l"(src) : "memory");
}
#define CP_COMMIT() asm volatile("cp.async.commit_group;" ::: "memory")

__device__ __forceinline__ uint32_t f2tf32(float v) {
    uint32_t r;
    asm("cvt.rna.tf32.f32 %0, %1;" : "=r"(r) : "f"(v));
    return r;
}
__device__ __forceinline__ float tf32f(float v) {
    return __uint_as_float(f2tf32(v));
}

__device__ __forceinline__ void mma_tf32(
    float& c0, float& c1, float& c2, float& c3,
    uint32_t a0, uint32_t a1, uint32_t a2, uint32_t a3,
    uint32_t b0, uint32_t b1)
{
    asm volatile(
        "mma.sync.aligned.m16n8k8.row.col.f32.tf32.tf32.f32 "
        "{%0,%1,%2,%3}, {%4,%5,%6,%7}, {%8,%9}, {%0,%1,%2,%3};"
        : "+f"(c0), "+f"(c1), "+f"(c2), "+f"(c3)
        : "r"(a0), "r"(a1), "r"(a2), "r"(a3), "r"(b0), "r"(b1));
}

// ===========================================================================
// fused tf32 pre-conversion of x, qkv_w, out_w (one launch)
// ===========================================================================
#define N4_X  (M_ * C_ / 4)
#define N4_W1 (QKV_N * C_ / 4)
#define N4_W2 (C_ * C_ / 4)
#define N4_ALL (N4_X + N4_W1 + N4_W2)

__global__ void __launch_bounds__(256) cvt_tf32_all(
    const float4* __restrict__ x,  float4* __restrict__ xo,
    const float4* __restrict__ w1, float4* __restrict__ w1o,
    const float4* __restrict__ w2, float4* __restrict__ w2o)
{
    int i = blockIdx.x * blockDim.x + threadIdx.x;
    const float4* src;
    float4* dst;
    int k;
    if (i < N4_X)              { src = x;  dst = xo;  k = i; }
    else if (i < N4_X + N4_W1) { src = w1; dst = w1o; k = i - N4_X; }
    else if (i < N4_ALL)       { src = w2; dst = w2o; k = i - N4_X - N4_W1; }
    else return;
    float4 v = src[k];
    v.x = tf32f(v.x); v.y = tf32f(v.y);
    v.z = tf32f(v.z); v.w = tf32f(v.w);
    dst[k] = v;
}

// ===========================================================================
// tf32 mma.sync NT GEMM — round-7 config (measured best: 16 warps/SM).
// CTA 128x128x32, 256 threads = 8 warps (2x4), warp tile 64x32,
// 2-stage cp.async, 2 CTAs/SM. Conflict-free float2 LDS (LDK=40).
// ===========================================================================
#define BM 128
#define BN 128
#define BK 32
#define LDK 40
#define STG (BM * LDK)                   // 5120 floats
#define NSTG 2
#define GEMM_SMEM (NSTG * 2 * STG * 4)   // 81920 bytes

template<bool CVT_OUT>
__global__ void __launch_bounds__(256, 2) gemm_mma_kernel(
    const float* __restrict__ A, const float* __restrict__ W,
    const float* __restrict__ bias, float* __restrict__ Cmat,
    int M, int N, int K)
{
    extern __shared__ __align__(16) float smf[];
    const uint32_t sb = smem_u32(smf);

    const int tid  = threadIdx.x;
    const int lane = tid & 31;
    const int wid  = tid >> 5;
    const int wm   = (wid & 1) * 64;
    const int wn   = (wid >> 1) * 32;
    const int g    = lane >> 2;
    const int tg   = lane & 3;

    const int m0 = blockIdx.y * BM;
    const int n0 = blockIdx.x * BN;
    const int NK = K / BK;

    const float* Abase = A + (size_t)m0 * K;
    const float* Wbase = W + (size_t)n0 * K;

    auto load_stage = [&](int kc) {
        const int st = kc % NSTG;
        const uint32_t sA = sb + st * 2 * STG * 4;
        const uint32_t sB = sA + STG * 4;
        const int kOff = kc * BK;
        #pragma unroll
        for (int t = 0; t < 4; t++) {
            int idx = tid + t * 256;
            int r = idx >> 3;
            int c = idx & 7;
            uint32_t off = (uint32_t)(r * LDK + c * 4) * 4;
            cp16(sA + off, Abase + (size_t)r * K + kOff + c * 4);
            cp16(sB + off, Wbase + (size_t)r * K + kOff + c * 4);
        }
        CP_COMMIT();
    };

    float acc[4][4][4] = {};

    load_stage(0);
    if (NK > 1) load_stage(1);

    for (int kc = 0; kc < NK; kc++) {
        if (kc + 1 < NK) asm volatile("cp.async.wait_group 1;" ::: "memory");
        else             asm volatile("cp.async.wait_group 0;" ::: "memory");
        __syncthreads();

        const int st = kc % NSTG;
        const float* As = smf + st * 2 * STG;
        const float* Bs = As + STG;

        #pragma unroll
        for (int ks = 0; ks < 4; ks++) {
            const int kk = ks * 8;
            uint32_t af[4][4], bf[4][2];
            #pragma unroll
            for (int i = 0; i < 4; i++) {
                const float* ap = As + (wm + i * 16 + g) * LDK + kk + tg * 2;
                float2 lo = *(const float2*)ap;
                float2 hi = *(const float2*)(ap + 8 * LDK);
                af[i][0] = __float_as_uint(lo.x);
                af[i][2] = __float_as_uint(lo.y);
                af[i][1] = __float_as_uint(hi.x);
                af[i][3] = __float_as_uint(hi.y);
            }
            #pragma unroll
            for (int j = 0; j < 4; j++) {
                float2 bb = *(const float2*)
                    (Bs + (wn + j * 8 + g) * LDK + kk + tg * 2);
                bf[j][0] = __float_as_uint(bb.x);
                bf[j][1] = __float_as_uint(bb.y);
            }
            #pragma unroll
            for (int i = 0; i < 4; i++)
                #pragma unroll
                for (int j = 0; j < 4; j++)
                    mma_tf32(acc[i][j][0], acc[i][j][1],
                             acc[i][j][2], acc[i][j][3],
                             af[i][0], af[i][1], af[i][2], af[i][3],
                             bf[j][0], bf[j][1]);
        }
        __syncthreads();

        if (kc + 2 < NK) load_stage(kc + 2);
    }

    #pragma unroll
    for (int i = 0; i < 4; i++) {
        const int row = m0 + wm + i * 16 + g;
        #pragma unroll
        for (int j = 0; j < 4; j++) {
            const int col = n0 + wn + j * 8 + tg * 2;
            float b0 = __ldg(bias + col);
            float b1 = __ldg(bias + col + 1);
            float2 v0, v1;
            if (CVT_OUT) {
                v0 = make_float2(tf32f(acc[i][j][0] + b0),
                                 tf32f(acc[i][j][1] + b1));
                v1 = make_float2(tf32f(acc[i][j][2] + b0),
                                 tf32f(acc[i][j][3] + b1));
            } else {
                v0 = make_float2(acc[i][j][0] + b0, acc[i][j][1] + b1);
                v1 = make_float2(acc[i][j][2] + b0, acc[i][j][3] + b1);
            }
            *(float2*)&Cmat[(size_t)row * N + col] = v0;
            *(float2*)&Cmat[(size_t)(row + 8) * N + col] = v1;
        }
    }
}

// ===========================================================================
// Tensor-core flash attention (tf32, causal).
// CTA = (b, h, 128-row q-block), 128 threads = 4 warps x 32 q-rows.
// Smem 108.5KB -> 2 CTAs/SM: one CTA's softmax (MUFU-heavy) overlaps the
// other CTA's MMA phases. K-fragments/V-scalars each feed 2 m-tiles.
// ===========================================================================
#define QB 128
#define QLD 72
#define KLD 72
#define VLD 68
#define K_TILE (64 * KLD)                        // 4608 floats
#define V_TILE (64 * VLD)                        // 4352 floats
#define Q_FLOATS (QB * QLD)                      // 9216 floats
#define KS_BASE  Q_FLOATS
#define VS_BASE  (Q_FLOATS + 2 * K_TILE)
#define ATT_SMEM ((VS_BASE + 2 * V_TILE) * 4)    // 108544 B

__global__ void __launch_bounds__(128, 2) attn_tc_kernel(
    const float* __restrict__ qkv, float* __restrict__ ctx)
{
    extern __shared__ __align__(16) float sm[];
    float* Qs = sm;
    const uint32_t sb = smem_u32(sm);

    const int tid  = threadIdx.x;
    const int lane = tid & 31;
    const int wid  = tid >> 5;
    const int g    = lane >> 2;
    const int tg   = lane & 3;
    const int wm   = wid * 32;                   // warp covers 32 q-rows

    const int bh = blockIdx.x;
    const int b  = bh >> 4;
    const int h  = bh & 15;
    const int qblock = 15 - (int)blockIdx.y;     // heavy blocks first
    const int q0 = qblock << 7;                  // * 128
    const int nk = (qblock + 1) * 2;             // causal k-tiles (64-wide)

    const size_t base = (size_t)b * T_ * QKV_N + (size_t)h * D_;

    auto load_k = [&](int fbase, const float* gsrc) {
        #pragma unroll
        for (int t = 0; t < 8; t++) {
            int idx = tid + t * 128;
            int r = idx >> 4;
            int c4 = (idx & 15) << 2;
            cp16(sb + (uint32_t)(fbase + r * KLD + c4) * 4,
                 gsrc + (size_t)r * QKV_N + c4);
        }
    };
    auto load_v = [&](int fbase, const float* gsrc) {
        #pragma unroll
        for (int t = 0; t < 8; t++) {
            int idx = tid + t * 128;
            int r = idx >> 4;
            int c4 = (idx & 15) << 2;
            cp16(sb + (uint32_t)(fbase + r * VLD + c4) * 4,
                 gsrc + (size_t)r * QKV_N + c4);
        }
    };

    {
        const float* qsrc = qkv + base + (size_t)q0 * QKV_N;
        #pragma unroll
        for (int t = 0; t < 16; t++) {
            int idx = tid + t * 128;
            int r = idx >> 4;
            int c4 = (idx & 15) << 2;
            cp16(sb + (uint32_t)(r * QLD + c4) * 4,
                 qsrc + (size_t)r * QKV_N + c4);
        }
        load_k(KS_BASE, qkv + base + C_);
        load_v(VS_BASE, qkv + base + 2 * C_);
        CP_COMMIT();
        load_k(KS_BASE + K_TILE, qkv + base + (size_t)64 * QKV_N + C_);
        load_v(VS_BASE + V_TILE, qkv + base + (size_t)64 * QKV_N + 2 * C_);
        CP_COMMIT();
    }
    asm volatile("cp.async.wait_group 1;" ::: "memory");
    __syncthreads();

    float o[2][8][4] = {};
    float mi[2][2] = {{-1e30f, -1e30f}, {-1e30f, -1e30f}};
    float li[2][2] = {};

    for (int it = 0; it < nk; it++) {
        const int cur = it & 1;
        const int k0 = it * 64;
        const float* Kb = sm + KS_BASE + cur * K_TILE;
        const float* Vb = sm + VS_BASE + cur * V_TILE;

        if (k0 <= q0 + wm + 31) {
            // ---- S = Q K^T (K fragment reused by both m-tiles) ----
            float s[2][8][4] = {};
            #pragma unroll
            for (int ks = 0; ks < 8; ks++) {
                const int kk = ks * 8;
                uint32_t af[2][4];
                #pragma unroll
                for (int m2 = 0; m2 < 2; m2++) {
                    const float* qp =
                        Qs + (wm + m2 * 16 + g) * QLD + kk + tg * 2;
                    float2 qa = *(const float2*)qp;
                    float2 qb = *(const float2*)(qp + 8 * QLD);
                    af[m2][0] = __float_as_uint(qa.x);
                    af[m2][2] = __float_as_uint(qa.y);
                    af[m2][1] = __float_as_uint(qb.x);
                    af[m2][3] = __float_as_uint(qb.y);
                }
                #pragma unroll
                for (int j = 0; j < 8; j++) {
                    float2 kb2 = *(const float2*)
                        (Kb + (j * 8 + g) * KLD + kk + tg * 2);
                    uint32_t b0 = __float_as_uint(kb2.x);
                    uint32_t b1 = __float_as_uint(kb2.y);
                    #pragma unroll
                    for (int m2 = 0; m2 < 2; m2++)
                        mma_tf32(s[m2][j][0], s[m2][j][1],
                                 s[m2][j][2], s[m2][j][3],
                                 af[m2][0], af[m2][1], af[m2][2], af[m2][3],
                                 b0, b1);
                }
            }

            // ---- scale + causal mask + online softmax ----
            const bool diag = (k0 + 63 > q0 + wm);
            #pragma unroll
            for (int m2 = 0; m2 < 2; m2++) {
                #pragma unroll
                for (int h2 = 0; h2 < 2; h2++) {
                    const int rowg = q0 + wm + m2 * 16 + g + h2 * 8;
                    float mx = -1e30f;
                    #pragma unroll
                    for (int j = 0; j < 8; j++) {
                        float v0 = s[m2][j][h2 * 2 + 0] * 0.125f;
                        float v1 = s[m2][j][h2 * 2 + 1] * 0.125f;
                        if (diag) {
                            int col = k0 + j * 8 + tg * 2;
                            if (col > rowg)     v0 = -1e30f;
                            if (col + 1 > rowg) v1 = -1e30f;
                        }
                        s[m2][j][h2 * 2 + 0] = v0;
                        s[m2][j][h2 * 2 + 1] = v1;
                        mx = fmaxf(mx, fmaxf(v0, v1));
                    }
                    mx = fmaxf(mx, __shfl_xor_sync(0xffffffffu, mx, 1));
                    mx = fmaxf(mx, __shfl_xor_sync(0xffffffffu, mx, 2));

                    float mnew = fmaxf(mi[m2][h2], mx);
                    float alpha = __expf(mi[m2][h2] - mnew);
                    float rs = 0.0f;
                    #pragma unroll
                    for (int j = 0; j < 8; j++) {
                        float p0 = __expf(s[m2][j][h2 * 2 + 0] - mnew);
                        float p1 = __expf(s[m2][j][h2 * 2 + 1] - mnew);
                        s[m2][j][h2 * 2 + 0] = p0;
                        s[m2][j][h2 * 2 + 1] = p1;
                        rs += p0 + p1;
                        o[m2][j][h2 * 2 + 0] *= alpha;
                        o[m2][j][h2 * 2 + 1] *= alpha;
                    }
                    rs += __shfl_xor_sync(0xffffffffu, rs, 1);
                    rs += __shfl_xor_sync(0xffffffffu, rs, 2);
                    li[m2][h2] = li[m2][h2] * alpha + rs;
                    mi[m2][h2] = mnew;
                }
            }

            // ---- O += P V (V scalars reused by both m-tiles) ----
            #pragma unroll
            for (int j = 0; j < 8; j++) {
                uint32_t a[2][4];
                #pragma unroll
                for (int m2 = 0; m2 < 2; m2++) {
                    a[m2][0] = f2tf32(s[m2][j][0]);
                    a[m2][1] = f2tf32(s[m2][j][2]);
                    a[m2][2] = f2tf32(s[m2][j][1]);
                    a[m2][3] = f2tf32(s[m2][j][3]);
                }
                #pragma unroll
                for (int n = 0; n < 8; n++) {
                    uint32_t b0 = __float_as_uint(
                        Vb[(j * 8 + tg * 2) * VLD + n * 8 + g]);
                    uint32_t b1 = __float_as_uint(
                        Vb[(j * 8 + tg * 2 + 1) * VLD + n * 8 + g]);
                    #pragma unroll
                    for (int m2 = 0; m2 < 2; m2++)
                        mma_tf32(o[m2][n][0], o[m2][n][1],
                                 o[m2][n][2], o[m2][n][3],
                                 a[m2][0], a[m2][1], a[m2][2], a[m2][3],
                                 b0, b1);
                }
            }
        }
        __syncthreads();

        if (it + 2 < nk) {
            const size_t roff = base + (size_t)(it + 2) * 64 * QKV_N;
            load_k(KS_BASE + cur * K_TILE, qkv + roff + C_);
            load_v(VS_BASE + cur * V_TILE, qkv + roff + 2 * C_);
            CP_COMMIT();
        }
        if (it + 1 < nk) {
            if (it + 2 < nk) asm volatile("cp.async.wait_group 1;" ::: "memory");
            else             asm volatile("cp.async.wait_group 0;" ::: "memory");
            __syncthreads();
        }
    }

    // ---- epilogue: tf32-rounded ctx (feeds tf32 out-proj) ----
    #pragma unroll
    for (int m2 = 0; m2 < 2; m2++) {
        #pragma unroll
        for (int h2 = 0; h2 < 2; h2++) {
            const float inv = 1.0f / li[m2][h2];
            const size_t row =
                (size_t)(b * T_ + q0 + wm + m2 * 16 + g + h2 * 8);
            #pragma unroll
            for (int n = 0; n < 8; n++) {
                float2 v = make_float2(tf32f(o[m2][n][h2 * 2 + 0] * inv),
                                       tf32f(o[m2][n][h2 * 2 + 1] * inv));
                *(float2*)&ctx[row * C_ + h * D_ + n * 8 + tg * 2] = v;
            }
        }
    }
}

// ---------------------------------------------------------------------------
// Launch
// ---------------------------------------------------------------------------
extern "C" void kernel_launch(void* const* d_in, const int* in_sizes, int n_in,
                              void* d_out, int out_size)
{
    const float* x      = (const float*)d_in[0];
    const float* qkv_w  = (const float*)d_in[1];
    const float* qkv_b  = (const float*)d_in[2];
    const float* out_w  = (const float*)d_in[3];
    const float* out_b  = (const float*)d_in[4];
    float* out = (float*)d_out;

    float *qkv_ptr, *ctx_ptr, *xc_ptr, *w1_ptr, *w2_ptr;
    cudaGetSymbolAddress((void**)&qkv_ptr, g_qkv);
    cudaGetSymbolAddress((void**)&ctx_ptr, g_ctx);
    cudaGetSymbolAddress((void**)&xc_ptr, g_xc);
    cudaGetSymbolAddress((void**)&w1_ptr, g_w1);
    cudaGetSymbolAddress((void**)&w2_ptr, g_w2);

    cudaFuncSetAttribute(gemm_mma_kernel<true>,
                         cudaFuncAttributeMaxDynamicSharedMemorySize, GEMM_SMEM);
    cudaFuncSetAttribute(gemm_mma_kernel<false>,
                         cudaFuncAttributeMaxDynamicSharedMemorySize, GEMM_SMEM);
    cudaFuncSetAttribute(attn_tc_kernel,
                         cudaFuncAttributeMaxDynamicSharedMemorySize, ATT_SMEM);

    // 0) fused tf32 pre-conversion
    cvt_tf32_all<<<(N4_ALL + 255) / 256, 256>>>(
        (const float4*)x, (float4*)xc_ptr,
        (const float4*)qkv_w, (float4*)w1_ptr,
        (const float4*)out_w, (float4*)w2_ptr);

    // 1) QKV projection
    gemm_mma_kernel<true><<<dim3(QKV_N / BN, M_ / BM), 256, GEMM_SMEM>>>(
        xc_ptr, w1_ptr, qkv_b, qkv_ptr, M_, QKV_N, C_);

    // 2) causal flash attention (128-row q-blocks, 2 CTAs/SM)
    attn_tc_kernel<<<dim3(H_ * B_, T_ / QB), 128, ATT_SMEM>>>(qkv_ptr, ctx_ptr);

    // 3) output projection
    gemm_mma_kernel<false><<<dim3(C_ / BN, M_ / BM), 256, GEMM_SMEM>>>(
        ctx_ptr, w2_ptr, out_b, out, M_, C_, C_);
}

// round 10
// speedup vs baseline: 1.0834x; 1.0834x over previous
#include <cuda_runtime.h>
#include <cuda_bf16.h>
#include <cstdint>
#include <math.h>

// Problem constants
#define B_ 4
#define T_ 2048
#define C_ 1024
#define H_ 16
#define D_ 64
#define M_ (B_ * T_)          // 8192 rows
#define QKV_N (3 * C_)        // 3072

// Scratch (tf32 bit patterns in f32 containers, except final output)
__device__ float g_qkv[(size_t)M_ * QKV_N];
__device__ float g_ctx[(size_t)M_ * C_];
__device__ float g_xc[(size_t)M_ * C_];
__device__ float g_w1[(size_t)QKV_N * C_];
__device__ float g_w2[(size_t)C_ * C_];

// ===========================================================================
// helpers
// ===========================================================================
__device__ __forceinline__ uint32_t smem_u32(const void* p) {
    uint32_t a;
    asm("{ .reg .u64 t; cvta.to.shared.u64 t, %1; cvt.u32.u64 %0, t; }"
        : "=r"(a) : "l"(p));
    return a;
}

__device__ __forceinline__ void cp16(uint32_t dst, const void* src) {
    asm volatile("cp.async.cg.shared.global [%0], [%1], 16;"
        :: "r"(dst), "l"(src) : "memory");
}
#define CP_COMMIT() asm volatile("cp.async.commit_group;" ::: "memory")

__device__ __forceinline__ uint32_t f2tf32(float v) {
    uint32_t r;
    asm("cvt.rna.tf32.f32 %0, %1;" : "=r"(r) : "f"(v));
    return r;
}
__device__ __forceinline__ float tf32f(float v) {
    return __uint_as_float(f2tf32(v));
}

__device__ __forceinline__ void mma_tf32(
    float& c0, float& c1, float& c2, float& c3,
    uint32_t a0, uint32_t a1, uint32_t a2, uint32_t a3,
    uint32_t b0, uint32_t b1)
{
    asm volatile(
        "mma.sync.aligned.m16n8k8.row.col.f32.tf32.tf32.f32 "
        "{%0,%1,%2,%3}, {%4,%5,%6,%7}, {%8,%9}, {%0,%1,%2,%3};"
        : "+f"(c0), "+f"(c1), "+f"(c2), "+f"(c3)
        : "r"(a0), "r"(a1), "r"(a2), "r"(a3), "r"(b0), "r"(b1));
}

// ===========================================================================
// fused tf32 pre-conversion of x, qkv_w, out_w (one launch)
// ===========================================================================
#define N4_X  (M_ * C_ / 4)
#define N4_W1 (QKV_N * C_ / 4)
#define N4_W2 (C_ * C_ / 4)
#define N4_ALL (N4_X + N4_W1 + N4_W2)

__global__ void __launch_bounds__(256) cvt_tf32_all(
    const float4* __restrict__ x,  float4* __restrict__ xo,
    const float4* __restrict__ w1, float4* __restrict__ w1o,
    const float4* __restrict__ w2, float4* __restrict__ w2o)
{
    int i = blockIdx.x * blockDim.x + threadIdx.x;
    const float4* src;
    float4* dst;
    int k;
    if (i < N4_X)              { src = x;  dst = xo;  k = i; }
    else if (i < N4_X + N4_W1) { src = w1; dst = w1o; k = i - N4_X; }
    else if (i < N4_ALL)       { src = w2; dst = w2o; k = i - N4_X - N4_W1; }
    else return;
    float4 v = src[k];
    v.x = tf32f(v.x); v.y = tf32f(v.y);
    v.z = tf32f(v.z); v.w = tf32f(v.w);
    dst[k] = v;
}

// ===========================================================================
// tf32 mma.sync NT GEMM. CTA 128x128x32, 256 threads = 8 warps (2x4),
// warp tile 64x32, 2 CTAs/SM. XOR-swizzled smem (chunk c of row r stored
// at c ^ ((r&3)<<1)) -> no padding (32 words/row), conflict-free fragment
// LDS.64, 3-stage cp.async pipeline, ONE __syncthreads per k-iter.
// ===========================================================================
#define BM 128
#define BN 128
#define BK 32
#define STGW (BM * BK)                   // 4096 words per matrix per stage
#define NSTG 3
#define GEMM_SMEM (NSTG * 2 * STGW * 4)  // 98304 bytes

template<bool CVT_OUT>
__global__ void __launch_bounds__(256, 2) gemm_mma_kernel(
    const float* __restrict__ A, const float* __restrict__ W,
    const float* __restrict__ bias, float* __restrict__ Cmat,
    int M, int N, int K)
{
    extern __shared__ __align__(16) float smf[];
    const uint32_t sb = smem_u32(smf);

    const int tid  = threadIdx.x;
    const int lane = tid & 31;
    const int wid  = tid >> 5;
    const int wm   = (wid & 1) * 64;
    const int wn   = (wid >> 1) * 32;
    const int g    = lane >> 2;
    const int tg   = lane & 3;

    const int m0 = blockIdx.y * BM;
    const int n0 = blockIdx.x * BN;
    const int NK = K / BK;

    const float* Abase = A + (size_t)m0 * K;
    const float* Wbase = W + (size_t)n0 * K;

    // loop-invariant swizzled fragment word-offsets within a row
    // koff[ks] = ((2ks + (tg>>1)) ^ ((g&3)<<1)) * 4 + (tg&1)*2
    const int xg = (g & 3) << 1;
    int koff[4];
    #pragma unroll
    for (int ks = 0; ks < 4; ks++)
        koff[ks] = (((2 * ks + (tg >> 1)) ^ xg) << 2) + ((tg & 1) << 1);

    auto load_stage = [&](int kc) {
        const int st = kc % NSTG;
        const uint32_t sA = sb + (uint32_t)st * 2 * STGW * 4;
        const uint32_t sB = sA + STGW * 4;
        const int kOff = kc * BK;
        #pragma unroll
        for (int t = 0; t < 4; t++) {
            int idx = tid + t * 256;
            int r = idx >> 3;              // row 0..127
            int c = idx & 7;               // 16B chunk
            uint32_t off =
                (uint32_t)(r * 32 + ((c ^ ((r & 3) << 1)) << 2)) * 4;
            cp16(sA + off, Abase + (size_t)r * K + kOff + c * 4);
            cp16(sB + off, Wbase + (size_t)r * K + kOff + c * 4);
        }
        CP_COMMIT();
    };

    float acc[4][4][4] = {};

    load_stage(0);
    if (NK > 1) load_stage(1);

    for (int kc = 0; kc < NK; kc++) {
        if (kc + 1 < NK) asm volatile("cp.async.wait_group 1;" ::: "memory");
        else             asm volatile("cp.async.wait_group 0;" ::: "memory");
        __syncthreads();

        const int st = kc % NSTG;
        const float* As = smf + st * 2 * STGW;
        const float* Bs = As + STGW;

        #pragma unroll
        for (int ks = 0; ks < 4; ks++) {
            uint32_t af[4][4], bf[4][2];
            #pragma unroll
            for (int i = 0; i < 4; i++) {
                const float* ap = As + (wm + i * 16 + g) * 32 + koff[ks];
                float2 lo = *(const float2*)ap;
                float2 hi = *(const float2*)(ap + 8 * 32);
                af[i][0] = __float_as_uint(lo.x);
                af[i][2] = __float_as_uint(lo.y);
                af[i][1] = __float_as_uint(hi.x);
                af[i][3] = __float_as_uint(hi.y);
            }
            #pragma unroll
            for (int j = 0; j < 4; j++) {
                float2 bb = *(const float2*)
                    (Bs + (wn + j * 8 + g) * 32 + koff[ks]);
                bf[j][0] = __float_as_uint(bb.x);
                bf[j][1] = __float_as_uint(bb.y);
            }
            #pragma unroll
            for (int i = 0; i < 4; i++)
                #pragma unroll
                for (int j = 0; j < 4; j++)
                    mma_tf32(acc[i][j][0], acc[i][j][1],
                             acc[i][j][2], acc[i][j][3],
                             af[i][0], af[i][1], af[i][2], af[i][3],
                             bf[j][0], bf[j][1]);
        }

        // prefetch stage kc+2 (overwrites the stage consumed at iter kc-1;
        // the sync above guarantees all warps are past it)
        if (kc + 2 < NK) load_stage(kc + 2);
    }

    #pragma unroll
    for (int i = 0; i < 4; i++) {
        const int row = m0 + wm + i * 16 + g;
        #pragma unroll
        for (int j = 0; j < 4; j++) {
            const int col = n0 + wn + j * 8 + tg * 2;
            float b0 = __ldg(bias + col);
            float b1 = __ldg(bias + col + 1);
            float2 v0, v1;
            if (CVT_OUT) {
                v0 = make_float2(tf32f(acc[i][j][0] + b0),
                                 tf32f(acc[i][j][1] + b1));
                v1 = make_float2(tf32f(acc[i][j][2] + b0),
                                 tf32f(acc[i][j][3] + b1));
            } else {
                v0 = make_float2(acc[i][j][0] + b0, acc[i][j][1] + b1);
                v1 = make_float2(acc[i][j][2] + b0, acc[i][j][3] + b1);
            }
            *(float2*)&Cmat[(size_t)row * N + col] = v0;
            *(float2*)&Cmat[(size_t)(row + 8) * N + col] = v1;
        }
    }
}

// ===========================================================================
// Tensor-core flash attention (tf32, causal) — round-9 config (verified).
// CTA = (b, h, 128-row q-block), 128 threads = 4 warps x 32 q-rows,
// 2 CTAs/SM.
// ===========================================================================
#define QB 128
#define QLD 72
#define KLD 72
#define VLD 68
#define K_TILE (64 * KLD)
#define V_TILE (64 * VLD)
#define Q_FLOATS (QB * QLD)
#define KS_BASE  Q_FLOATS
#define VS_BASE  (Q_FLOATS + 2 * K_TILE)
#define ATT_SMEM ((VS_BASE + 2 * V_TILE) * 4)    // 108544 B

__global__ void __launch_bounds__(128, 2) attn_tc_kernel(
    const float* __restrict__ qkv, float* __restrict__ ctx)
{
    extern __shared__ __align__(16) float sm[];
    float* Qs = sm;
    const uint32_t sb = smem_u32(sm);

    const int tid  = threadIdx.x;
    const int lane = tid & 31;
    const int wid  = tid >> 5;
    const int g    = lane >> 2;
    const int tg   = lane & 3;
    const int wm   = wid * 32;

    const int bh = blockIdx.x;
    const int b  = bh >> 4;
    const int h  = bh & 15;
    const int qblock = 15 - (int)blockIdx.y;
    const int q0 = qblock << 7;
    const int nk = (qblock + 1) * 2;

    const size_t base = (size_t)b * T_ * QKV_N + (size_t)h * D_;

    auto load_k = [&](int fbase, const float* gsrc) {
        #pragma unroll
        for (int t = 0; t < 8; t++) {
            int idx = tid + t * 128;
            int r = idx >> 4;
            int c4 = (idx & 15) << 2;
            cp16(sb + (uint32_t)(fbase + r * KLD + c4) * 4,
                 gsrc + (size_t)r * QKV_N + c4);
        }
    };
    auto load_v = [&](int fbase, const float* gsrc) {
        #pragma unroll
        for (int t = 0; t < 8; t++) {
            int idx = tid + t * 128;
            int r = idx >> 4;
            int c4 = (idx & 15) << 2;
            cp16(sb + (uint32_t)(fbase + r * VLD + c4) * 4,
                 gsrc + (size_t)r * QKV_N + c4);
        }
    };

    {
        const float* qsrc = qkv + base + (size_t)q0 * QKV_N;
        #pragma unroll
        for (int t = 0; t < 16; t++) {
            int idx = tid + t * 128;
            int r = idx >> 4;
            int c4 = (idx & 15) << 2;
            cp16(sb + (uint32_t)(r * QLD + c4) * 4,
                 qsrc + (size_t)r * QKV_N + c4);
        }
        load_k(KS_BASE, qkv + base + C_);
        load_v(VS_BASE, qkv + base + 2 * C_);
        CP_COMMIT();
        load_k(KS_BASE + K_TILE, qkv + base + (size_t)64 * QKV_N + C_);
        load_v(VS_BASE + V_TILE, qkv + base + (size_t)64 * QKV_N + 2 * C_);
        CP_COMMIT();
    }
    asm volatile("cp.async.wait_group 1;" ::: "memory");
    __syncthreads();

    float o[2][8][4] = {};
    float mi[2][2] = {{-1e30f, -1e30f}, {-1e30f, -1e30f}};
    float li[2][2] = {};

    for (int it = 0; it < nk; it++) {
        const int cur = it & 1;
        const int k0 = it * 64;
        const float* Kb = sm + KS_BASE + cur * K_TILE;
        const float* Vb = sm + VS_BASE + cur * V_TILE;

        if (k0 <= q0 + wm + 31) {
            // ---- S = Q K^T (K fragment reused by both m-tiles) ----
            float s[2][8][4] = {};
            #pragma unroll
            for (int ks = 0; ks < 8; ks++) {
                const int kk = ks * 8;
                uint32_t af[2][4];
                #pragma unroll
                for (int m2 = 0; m2 < 2; m2++) {
                    const float* qp =
                        Qs + (wm + m2 * 16 + g) * QLD + kk + tg * 2;
                    float2 qa = *(const float2*)qp;
                    float2 qb = *(const float2*)(qp + 8 * QLD);
                    af[m2][0] = __float_as_uint(qa.x);
                    af[m2][2] = __float_as_uint(qa.y);
                    af[m2][1] = __float_as_uint(qb.x);
                    af[m2][3] = __float_as_uint(qb.y);
                }
                #pragma unroll
                for (int j = 0; j < 8; j++) {
                    float2 kb2 = *(const float2*)
                        (Kb + (j * 8 + g) * KLD + kk + tg * 2);
                    uint32_t b0 = __float_as_uint(kb2.x);
                    uint32_t b1 = __float_as_uint(kb2.y);
                    #pragma unroll
                    for (int m2 = 0; m2 < 2; m2++)
                        mma_tf32(s[m2][j][0], s[m2][j][1],
                                 s[m2][j][2], s[m2][j][3],
                                 af[m2][0], af[m2][1], af[m2][2], af[m2][3],
                                 b0, b1);
                }
            }

            // ---- scale + causal mask + online softmax ----
            const bool diag = (k0 + 63 > q0 + wm);
            #pragma unroll
            for (int m2 = 0; m2 < 2; m2++) {
                #pragma unroll
                for (int h2 = 0; h2 < 2; h2++) {
                    const int rowg = q0 + wm + m2 * 16 + g + h2 * 8;
                    float mx = -1e30f;
                    #pragma unroll
                    for (int j = 0; j < 8; j++) {
                        float v0 = s[m2][j][h2 * 2 + 0] * 0.125f;
                        float v1 = s[m2][j][h2 * 2 + 1] * 0.125f;
                        if (diag) {
                            int col = k0 + j * 8 + tg * 2;
                            if (col > rowg)     v0 = -1e30f;
                            if (col + 1 > rowg) v1 = -1e30f;
                        }
                        s[m2][j][h2 * 2 + 0] = v0;
                        s[m2][j][h2 * 2 + 1] = v1;
                        mx = fmaxf(mx, fmaxf(v0, v1));
                    }
                    mx = fmaxf(mx, __shfl_xor_sync(0xffffffffu, mx, 1));
                    mx = fmaxf(mx, __shfl_xor_sync(0xffffffffu, mx, 2));

                    float mnew = fmaxf(mi[m2][h2], mx);
                    float alpha = __expf(mi[m2][h2] - mnew);
                    float rs = 0.0f;
                    #pragma unroll
                    for (int j = 0; j < 8; j++) {
                        float p0 = __expf(s[m2][j][h2 * 2 + 0] - mnew);
                        float p1 = __expf(s[m2][j][h2 * 2 + 1] - mnew);
                        s[m2][j][h2 * 2 + 0] = p0;
                        s[m2][j][h2 * 2 + 1] = p1;
                        rs += p0 + p1;
                        o[m2][j][h2 * 2 + 0] *= alpha;
                        o[m2][j][h2 * 2 + 1] *= alpha;
                    }
                    rs += __shfl_xor_sync(0xffffffffu, rs, 1);
                    rs += __shfl_xor_sync(0xffffffffu, rs, 2);
                    li[m2][h2] = li[m2][h2] * alpha + rs;
                    mi[m2][h2] = mnew;
                }
            }

            // ---- O += P V (V scalars reused by both m-tiles) ----
            #pragma unroll
            for (int j = 0; j < 8; j++) {
                uint32_t a[2][4];
                #pragma unroll
                for (int m2 = 0; m2 < 2; m2++) {
                    a[m2][0] = f2tf32(s[m2][j][0]);
                    a[m2][1] = f2tf32(s[m2][j][2]);
                    a[m2][2] = f2tf32(s[m2][j][1]);
                    a[m2][3] = f2tf32(s[m2][j][3]);
                }
                #pragma unroll
                for (int n = 0; n < 8; n++) {
                    uint32_t b0 = __float_as_uint(
                        Vb[(j * 8 + tg * 2) * VLD + n * 8 + g]);
                    uint32_t b1 = __float_as_uint(
                        Vb[(j * 8 + tg * 2 + 1) * VLD + n * 8 + g]);
                    #pragma unroll
                    for (int m2 = 0; m2 < 2; m2++)
                        mma_tf32(o[m2][n][0], o[m2][n][1],
                                 o[m2][n][2], o[m2][n][3],
                                 a[m2][0], a[m2][1], a[m2][2], a[m2][3],
                                 b0, b1);
                }
            }
        }
        __syncthreads();

        if (it + 2 < nk) {
            const size_t roff = base + (size_t)(it + 2) * 64 * QKV_N;
            load_k(KS_BASE + cur * K_TILE, qkv + roff + C_);
            load_v(VS_BASE + cur * V_TILE, qkv + roff + 2 * C_);
            CP_COMMIT();
        }
        if (it + 1 < nk) {
            if (it + 2 < nk) asm volatile("cp.async.wait_group 1;" ::: "memory");
            else             asm volatile("cp.async.wait_group 0;" ::: "memory");
            __syncthreads();
        }
    }

    // ---- epilogue: tf32-rounded ctx (feeds tf32 out-proj) ----
    #pragma unroll
    for (int m2 = 0; m2 < 2; m2++) {
        #pragma unroll
        for (int h2 = 0; h2 < 2; h2++) {
            const float inv = 1.0f / li[m2][h2];
            const size_t row =
                (size_t)(b * T_ + q0 + wm + m2 * 16 + g + h2 * 8);
            #pragma unroll
            for (int n = 0; n < 8; n++) {
                float2 v = make_float2(tf32f(o[m2][n][h2 * 2 + 0] * inv),
                                       tf32f(o[m2][n][h2 * 2 + 1] * inv));
                *(float2*)&ctx[row * C_ + h * D_ + n * 8 + tg * 2] = v;
            }
        }
    }
}

// ---------------------------------------------------------------------------
// Launch
// ---------------------------------------------------------------------------
extern "C" void kernel_launch(void* const* d_in, const int* in_sizes, int n_in,
                              void* d_out, int out_size)
{
    const float* x      = (const float*)d_in[0];
    const float* qkv_w  = (const float*)d_in[1];
    const float* qkv_b  = (const float*)d_in[2];
    const float* out_w  = (const float*)d_in[3];
    const float* out_b  = (const float*)d_in[4];
    float* out = (float*)d_out;

    float *qkv_ptr, *ctx_ptr, *xc_ptr, *w1_ptr, *w2_ptr;
    cudaGetSymbolAddress((void**)&qkv_ptr, g_qkv);
    cudaGetSymbolAddress((void**)&ctx_ptr, g_ctx);
    cudaGetSymbolAddress((void**)&xc_ptr, g_xc);
    cudaGetSymbolAddress((void**)&w1_ptr, g_w1);
    cudaGetSymbolAddress((void**)&w2_ptr, g_w2);

    cudaFuncSetAttribute(gemm_mma_kernel<true>,
                         cudaFuncAttributeMaxDynamicSharedMemorySize, GEMM_SMEM);
    cudaFuncSetAttribute(gemm_mma_kernel<false>,
                         cudaFuncAttributeMaxDynamicSharedMemorySize, GEMM_SMEM);
    cudaFuncSetAttribute(attn_tc_kernel,
                         cudaFuncAttributeMaxDynamicSharedMemorySize, ATT_SMEM);

    // 0) fused tf32 pre-conversion
    cvt_tf32_all<<<(N4_ALL + 255) / 256, 256>>>(
        (const float4*)x, (float4*)xc_ptr,
        (const float4*)qkv_w, (float4*)w1_ptr,
        (const float4*)out_w, (float4*)w2_ptr);

    // 1) QKV projection
    gemm_mma_kernel<true><<<dim3(QKV_N / BN, M_ / BM), 256, GEMM_SMEM>>>(
        xc_ptr, w1_ptr, qkv_b, qkv_ptr, M_, QKV_N, C_);

    // 2) causal flash attention
    attn_tc_kernel<<<dim3(H_ * B_, T_ / QB), 128, ATT_SMEM>>>(qkv_ptr, ctx_ptr);

    // 3) output projection
    gemm_mma_kernel<false><<<dim3(C_ / BN, M_ / BM), 256, GEMM_SMEM>>>(
        ctx_ptr, w2_ptr, out_b, out, M_, C_, C_);
}